// round 6
// baseline (speedup 1.0000x reference)
#include <cuda_runtime.h>
#include <cuda_bf16.h>

// ZBL repulsion energy, R6: distributed-smem Z table via 4-CTA clusters.
//
// R1/R2 ncu: L2=83% (LTS-bound). Gather traffic is sector-amplified 32x
// (1-byte random gathers -> 32B L2 sectors). Fix: hold the 500KB Z table in
// the combined smem of a 4-CTA cluster (4 x 128KB slices) and gather via
// mapa + ld.shared::cluster.u8 -> moves 1 byte at DSMEM rates, zero L2
// gather traffic. Remaining L2: 256MB streaming + 512MB atomic sectors.

#define KEHALF 7.199822675975274f
#define LOG2E  1.4426950408889634f
#define MAX_ATOMS 524288          // 4 * 131072; problem uses 500,000
#define SLICE_SHIFT 17
#define SLICE_BYTES 131072        // 128 KB per cluster CTA
#define CLUSTER 4
#define TPB 512
#define PPT 8                     // pairs per thread

__device__ unsigned char g_Z8[MAX_ATOMS];
__device__ float g_zlut[128];     // z = Z^sp(apow), indexed by Z
__device__ float g_c[12];         // b1..b4, c1n..c4n

__device__ __forceinline__ float ex2f(float x) {
    float y; asm("ex2.approx.ftz.f32 %0, %1;" : "=f"(y) : "f"(x)); return y;
}
__device__ __forceinline__ float frcpf(float x) {
    float y; asm("rcp.approx.ftz.f32 %0, %1;" : "=f"(y) : "f"(x)); return y;
}
__device__ __forceinline__ unsigned smem_u32(const void* p) {
    unsigned a;
    asm("{ .reg .u64 t; cvta.to.shared.u64 t, %1; cvt.u32.u64 %0, t; }"
        : "=r"(a) : "l"(p));
    return a;
}
// Gather one Z byte from the cluster-distributed table.
__device__ __forceinline__ unsigned dsmem_Z(unsigned slice_base, unsigned idx) {
    unsigned rank = idx >> SLICE_SHIFT;
    unsigned off  = idx & (SLICE_BYTES - 1);
    unsigned addr, v;
    asm("mapa.shared::cluster.u32 %0, %1, %2;"
        : "=r"(addr) : "r"(slice_base + off), "r"(rank));
    asm("ld.shared::cluster.u8 %0, [%1];" : "=r"(v) : "r"(addr));
    return v;
}

__global__ void prep_kernel(const float* __restrict__ Zf, int natoms,
                            const float* adiv, const float* apow,
                            const float* c1, const float* c2,
                            const float* c3, const float* c4,
                            const float* a1, const float* a2,
                            const float* a3, const float* a4) {
    int t = blockIdx.x * blockDim.x + threadIdx.x;
    if (t < MAX_ATOMS)
        g_Z8[t] = (t < natoms) ? (unsigned char)__float2int_rn(Zf[t]) : 0;

    if (blockIdx.x == 0) {
        if (threadIdx.x < 128) {
            float spapow = log1pf(expf(*apow));
            g_zlut[threadIdx.x] = (threadIdx.x == 0) ? 0.0f
                                : powf((float)threadIdx.x, spapow);
        }
        if (threadIdx.x == 0) {
            float spadiv = log1pf(expf(*adiv));
            float sa1 = log1pf(expf(*a1)), sa2 = log1pf(expf(*a2));
            float sa3 = log1pf(expf(*a3)), sa4 = log1pf(expf(*a4));
            float c1p = log1pf(expf(*c1)), c2p = log1pf(expf(*c2));
            float c3p = log1pf(expf(*c3)), c4p = log1pf(expf(*c4));
            float inv = 1.0f / (c1p + c2p + c3p + c4p);
            g_c[0] = sa1 * spadiv * LOG2E;  g_c[1] = sa2 * spadiv * LOG2E;
            g_c[2] = sa3 * spadiv * LOG2E;  g_c[3] = sa4 * spadiv * LOG2E;
            g_c[4] = c1p * inv; g_c[5] = c2p * inv;
            g_c[6] = c3p * inv; g_c[7] = c4p * inv;
        }
    }
}

struct PairConsts { float b1, b2, b3, b4, c1n, c2n, c3n, c4n; };

__device__ __forceinline__ void finish_pair(float r, float cv,
                                            unsigned zi, unsigned zj, int i,
                                            const float* __restrict__ s_z,
                                            const PairConsts& K,
                                            float* __restrict__ out) {
    float s  = s_z[zi] + s_z[zj];
    float t  = s * r;
    float f  = K.c1n * ex2f(-K.b1 * t)
             + K.c2n * ex2f(-K.b2 * t)
             + K.c3n * ex2f(-K.b3 * t)
             + K.c4n * ex2f(-K.b4 * t);
    float zz = (float)(zi * zj);
    atomicAdd(out + i, (KEHALF * cv * zz) * f * frcpf(r));
}

extern "C" __global__ void __launch_bounds__(TPB, 1) __cluster_dims__(CLUSTER, 1, 1)
pair_kernel(const float* __restrict__ rij, const float* __restrict__ cv,
            const int* __restrict__ ii, const int* __restrict__ jj,
            float* __restrict__ out, int P) {
    extern __shared__ unsigned char s_slice[];   // SLICE_BYTES
    __shared__ float s_z[128];
    __shared__ float s_c8[8];
    int tid = threadIdx.x;

    // Fill this CTA's 128KB slice of the Z table (coalesced 16B copies).
    unsigned rank;
    asm("mov.u32 %0, %%cluster_ctarank;" : "=r"(rank));
    {
        const uint4* src = (const uint4*)(g_Z8 + (size_t)rank * SLICE_BYTES);
        uint4* dst = (uint4*)s_slice;
        #pragma unroll 4
        for (int k = tid; k < SLICE_BYTES / 16; k += TPB) dst[k] = src[k];
    }
    if (tid < 128) s_z[tid] = g_zlut[tid];
    if (tid < 8)   s_c8[tid] = g_c[tid];
    __syncthreads();
    asm volatile("barrier.cluster.arrive.aligned;" ::: "memory");
    asm volatile("barrier.cluster.wait.aligned;"   ::: "memory");

    PairConsts K;
    K.b1 = s_c8[0]; K.b2 = s_c8[1]; K.b3 = s_c8[2]; K.b4 = s_c8[3];
    K.c1n = s_c8[4]; K.c2n = s_c8[5]; K.c3n = s_c8[6]; K.c4n = s_c8[7];

    unsigned sbase = smem_u32(s_slice);
    long base = ((long)blockIdx.x * TPB + tid) * PPT;

    if (base + PPT <= (long)P) {
        // Index vectors first -> issue all 16 DSMEM gathers for MLP.
        int4 iA = __ldcs((const int4*)(ii + base));
        int4 iB = __ldcs((const int4*)(ii + base + 4));
        int4 jA = __ldcs((const int4*)(jj + base));
        int4 jB = __ldcs((const int4*)(jj + base + 4));
        unsigned z[16];
        z[0]  = dsmem_Z(sbase, (unsigned)iA.x);
        z[1]  = dsmem_Z(sbase, (unsigned)iA.y);
        z[2]  = dsmem_Z(sbase, (unsigned)iA.z);
        z[3]  = dsmem_Z(sbase, (unsigned)iA.w);
        z[4]  = dsmem_Z(sbase, (unsigned)iB.x);
        z[5]  = dsmem_Z(sbase, (unsigned)iB.y);
        z[6]  = dsmem_Z(sbase, (unsigned)iB.z);
        z[7]  = dsmem_Z(sbase, (unsigned)iB.w);
        z[8]  = dsmem_Z(sbase, (unsigned)jA.x);
        z[9]  = dsmem_Z(sbase, (unsigned)jA.y);
        z[10] = dsmem_Z(sbase, (unsigned)jA.z);
        z[11] = dsmem_Z(sbase, (unsigned)jA.w);
        z[12] = dsmem_Z(sbase, (unsigned)jB.x);
        z[13] = dsmem_Z(sbase, (unsigned)jB.y);
        z[14] = dsmem_Z(sbase, (unsigned)jB.z);
        z[15] = dsmem_Z(sbase, (unsigned)jB.w);

        float4 rA = __ldcs((const float4*)(rij + base));
        float4 rB = __ldcs((const float4*)(rij + base + 4));
        float4 cA = __ldcs((const float4*)(cv + base));
        float4 cB = __ldcs((const float4*)(cv + base + 4));

        finish_pair(rA.x, cA.x, z[0], z[8],  iA.x, s_z, K, out);
        finish_pair(rA.y, cA.y, z[1], z[9],  iA.y, s_z, K, out);
        finish_pair(rA.z, cA.z, z[2], z[10], iA.z, s_z, K, out);
        finish_pair(rA.w, cA.w, z[3], z[11], iA.w, s_z, K, out);
        finish_pair(rB.x, cB.x, z[4], z[12], iB.x, s_z, K, out);
        finish_pair(rB.y, cB.y, z[5], z[13], iB.y, s_z, K, out);
        finish_pair(rB.z, cB.z, z[6], z[14], iB.z, s_z, K, out);
        finish_pair(rB.w, cB.w, z[7], z[15], iB.w, s_z, K, out);
    } else {
        for (long p = base; p < (long)P; ++p) {
            int i = ii[p], j = jj[p];
            unsigned zi = dsmem_Z(sbase, (unsigned)i);
            unsigned zj = dsmem_Z(sbase, (unsigned)j);
            finish_pair(rij[p], cv[p], zi, zj, i, s_z, K, out);
        }
    }

    // No CTA may exit while cluster peers might still gather from its slice.
    asm volatile("barrier.cluster.arrive.aligned;" ::: "memory");
    asm volatile("barrier.cluster.wait.aligned;"   ::: "memory");
}

extern "C" void kernel_launch(void* const* d_in, const int* in_sizes, int n_in,
                              void* d_out, int out_size) {
    const float* Zf   = (const float*)d_in[n_in - 15];
    const float* rij  = (const float*)d_in[n_in - 14];
    const float* cutv = (const float*)d_in[n_in - 13];
    const int*   ii   = (const int*)  d_in[n_in - 12];
    const int*   jj   = (const int*)  d_in[n_in - 11];
    const float* adiv = (const float*)d_in[n_in - 10];
    const float* apow = (const float*)d_in[n_in - 9];
    const float* c1   = (const float*)d_in[n_in - 8];
    const float* c2   = (const float*)d_in[n_in - 7];
    const float* c3   = (const float*)d_in[n_in - 6];
    const float* c4   = (const float*)d_in[n_in - 5];
    const float* a1   = (const float*)d_in[n_in - 4];
    const float* a2   = (const float*)d_in[n_in - 3];
    const float* a3   = (const float*)d_in[n_in - 2];
    const float* a4   = (const float*)d_in[n_in - 1];

    int natoms = in_sizes[n_in - 15];
    int P      = in_sizes[n_in - 14];
    float* out = (float*)d_out;

    static int smem_set = 0;
    if (!smem_set) {
        cudaFuncSetAttribute((const void*)pair_kernel,
                             cudaFuncAttributeMaxDynamicSharedMemorySize,
                             SLICE_BYTES);
        smem_set = 1;
    }

    int pb = (MAX_ATOMS + 255) / 256;
    prep_kernel<<<pb, 256>>>(Zf, natoms, adiv, apow, c1, c2, c3, c4, a1, a2, a3, a4);

    cudaMemsetAsync(d_out, 0, (size_t)out_size * sizeof(float));

    long nthreads = ((long)P + PPT - 1) / PPT;
    int blocks = (int)((nthreads + TPB - 1) / TPB);
    blocks = (blocks + CLUSTER - 1) / CLUSTER * CLUSTER;   // cluster-divisible
    pair_kernel<<<blocks, TPB, SLICE_BYTES>>>(rij, cutv, ii, jj, out, P);
}

// round 7
// speedup vs baseline: 2.1437x; 2.1437x over previous
#include <cuda_runtime.h>
#include <cuda_bf16.h>

// ZBL repulsion energy, R7: hybrid gather — table head in CTA smem, tail via L1/L2.
//
// R1 model: 3 scattered L1tex wavefronts/pair (2 gathers + 1 RED), L1=81% L2=83%
// co-saturated. R6 (DSMEM cluster) removed L2 gather traffic but died on remote
// fabric latency/request rate (444us). R7: first 192KB of the 500KB Z table lives
// in LOCAL smem -> those gathers cost only LDS bank phases (no wavefronts, no L2
// sectors); the remaining 61% stay on the LDG/L1 path. wf/pair 3 -> 2.2.

#define KEHALF 7.199822675975274f
#define LOG2E  1.4426950408889634f
#define MAX_ATOMS 524288          // problem uses 500,000
#define SMEM_ATOMS 196608         // 192KB table head resident in smem
#define TPB 1024
#define PPT 4

__device__ unsigned char g_Z8[MAX_ATOMS];
__device__ float g_zlut[128];     // z = Z^sp(apow), indexed by Z
__device__ float g_c[12];         // b1..b4 (=sp(a_k)*sp(adiv)*log2e), c1n..c4n

__device__ __forceinline__ float ex2f(float x) {
    float y; asm("ex2.approx.ftz.f32 %0, %1;" : "=f"(y) : "f"(x)); return y;
}
__device__ __forceinline__ float frcpf(float x) {
    float y; asm("rcp.approx.ftz.f32 %0, %1;" : "=f"(y) : "f"(x)); return y;
}

__global__ void prep_kernel(const float* __restrict__ Zf, int natoms,
                            const float* adiv, const float* apow,
                            const float* c1, const float* c2,
                            const float* c3, const float* c4,
                            const float* a1, const float* a2,
                            const float* a3, const float* a4) {
    int t = blockIdx.x * blockDim.x + threadIdx.x;
    if (t < MAX_ATOMS)
        g_Z8[t] = (t < natoms) ? (unsigned char)__float2int_rn(Zf[t]) : 0;

    if (blockIdx.x == 0) {
        if (threadIdx.x < 128) {
            float spapow = log1pf(expf(*apow));
            g_zlut[threadIdx.x] = (threadIdx.x == 0) ? 0.0f
                                : powf((float)threadIdx.x, spapow);
        }
        if (threadIdx.x == 0) {
            float spadiv = log1pf(expf(*adiv));
            float sa1 = log1pf(expf(*a1)), sa2 = log1pf(expf(*a2));
            float sa3 = log1pf(expf(*a3)), sa4 = log1pf(expf(*a4));
            float c1p = log1pf(expf(*c1)), c2p = log1pf(expf(*c2));
            float c3p = log1pf(expf(*c3)), c4p = log1pf(expf(*c4));
            float inv = 1.0f / (c1p + c2p + c3p + c4p);
            g_c[0] = sa1 * spadiv * LOG2E;  g_c[1] = sa2 * spadiv * LOG2E;
            g_c[2] = sa3 * spadiv * LOG2E;  g_c[3] = sa4 * spadiv * LOG2E;
            g_c[4] = c1p * inv; g_c[5] = c2p * inv;
            g_c[6] = c3p * inv; g_c[7] = c4p * inv;
        }
    }
}

struct PairConsts { float b1, b2, b3, b4, c1n, c2n, c3n, c4n; };

// Z gather: smem head (LDS, no wavefronts) or global tail (L1/L2).
__device__ __forceinline__ unsigned gatherZ(const unsigned char* __restrict__ s_tab,
                                            unsigned idx) {
    if (idx < SMEM_ATOMS)
        return s_tab[idx];
    unsigned v;
    asm("ld.global.nc.L1::evict_last.u8 %0, [%1];" : "=r"(v) : "l"(g_Z8 + idx));
    return v;
}

__device__ __forceinline__ void finish_pair(float r, float cv,
                                            unsigned zi, unsigned zj, int i,
                                            const float* __restrict__ s_z,
                                            const PairConsts& K,
                                            float* __restrict__ out) {
    float s  = s_z[zi] + s_z[zj];
    float t  = s * r;
    float f  = K.c1n * ex2f(-K.b1 * t)
             + K.c2n * ex2f(-K.b2 * t)
             + K.c3n * ex2f(-K.b3 * t)
             + K.c4n * ex2f(-K.b4 * t);
    float zz = (float)(zi * zj);
    atomicAdd(out + i, (KEHALF * cv * zz) * f * frcpf(r));
}

extern "C" __global__ void __launch_bounds__(TPB, 1)
pair_kernel(const float* __restrict__ rij, const float* __restrict__ cv,
            const int* __restrict__ ii, const int* __restrict__ jj,
            float* __restrict__ out, int P) {
    extern __shared__ unsigned char s_tab[];     // SMEM_ATOMS bytes
    __shared__ float s_z[128];
    __shared__ float s_c8[8];
    int tid = threadIdx.x;

    // Fill the smem-resident table head (coalesced 16B copies).
    {
        const uint4* src = (const uint4*)g_Z8;
        uint4* dst = (uint4*)s_tab;
        #pragma unroll 4
        for (int k = tid; k < SMEM_ATOMS / 16; k += TPB) dst[k] = src[k];
    }
    if (tid < 128) s_z[tid] = g_zlut[tid];
    if (tid < 8)   s_c8[tid] = g_c[tid];
    __syncthreads();

    PairConsts K;
    K.b1 = s_c8[0]; K.b2 = s_c8[1]; K.b3 = s_c8[2]; K.b4 = s_c8[3];
    K.c1n = s_c8[4]; K.c2n = s_c8[5]; K.c3n = s_c8[6]; K.c4n = s_c8[7];

    long base = ((long)blockIdx.x * TPB + tid) * PPT;

    if (base + PPT <= (long)P) {
        // Indices first: issue all 8 gathers back-to-back for MLP.
        int4 i4 = __ldcs((const int4*)(ii + base));
        int4 j4 = __ldcs((const int4*)(jj + base));
        unsigned zi0 = gatherZ(s_tab, (unsigned)i4.x);
        unsigned zi1 = gatherZ(s_tab, (unsigned)i4.y);
        unsigned zi2 = gatherZ(s_tab, (unsigned)i4.z);
        unsigned zi3 = gatherZ(s_tab, (unsigned)i4.w);
        unsigned zj0 = gatherZ(s_tab, (unsigned)j4.x);
        unsigned zj1 = gatherZ(s_tab, (unsigned)j4.y);
        unsigned zj2 = gatherZ(s_tab, (unsigned)j4.z);
        unsigned zj3 = gatherZ(s_tab, (unsigned)j4.w);

        float4 r4 = __ldcs((const float4*)(rij + base));
        float4 c4 = __ldcs((const float4*)(cv + base));

        finish_pair(r4.x, c4.x, zi0, zj0, i4.x, s_z, K, out);
        finish_pair(r4.y, c4.y, zi1, zj1, i4.y, s_z, K, out);
        finish_pair(r4.z, c4.z, zi2, zj2, i4.z, s_z, K, out);
        finish_pair(r4.w, c4.w, zi3, zj3, i4.w, s_z, K, out);
    } else {
        for (long p = base; p < (long)P; ++p) {
            int i = ii[p], j = jj[p];
            unsigned zi = gatherZ(s_tab, (unsigned)i);
            unsigned zj = gatherZ(s_tab, (unsigned)j);
            finish_pair(rij[p], cv[p], zi, zj, i, s_z, K, out);
        }
    }
}

extern "C" void kernel_launch(void* const* d_in, const int* in_sizes, int n_in,
                              void* d_out, int out_size) {
    const float* Zf   = (const float*)d_in[n_in - 15];
    const float* rij  = (const float*)d_in[n_in - 14];
    const float* cutv = (const float*)d_in[n_in - 13];
    const int*   ii   = (const int*)  d_in[n_in - 12];
    const int*   jj   = (const int*)  d_in[n_in - 11];
    const float* adiv = (const float*)d_in[n_in - 10];
    const float* apow = (const float*)d_in[n_in - 9];
    const float* c1   = (const float*)d_in[n_in - 8];
    const float* c2   = (const float*)d_in[n_in - 7];
    const float* c3   = (const float*)d_in[n_in - 6];
    const float* c4   = (const float*)d_in[n_in - 5];
    const float* a1   = (const float*)d_in[n_in - 4];
    const float* a2   = (const float*)d_in[n_in - 3];
    const float* a3   = (const float*)d_in[n_in - 2];
    const float* a4   = (const float*)d_in[n_in - 1];

    int natoms = in_sizes[n_in - 15];
    int P      = in_sizes[n_in - 14];
    float* out = (float*)d_out;

    static int smem_set = 0;
    if (!smem_set) {
        cudaFuncSetAttribute((const void*)pair_kernel,
                             cudaFuncAttributeMaxDynamicSharedMemorySize,
                             SMEM_ATOMS);
        smem_set = 1;
    }

    int pb = (MAX_ATOMS + 255) / 256;
    prep_kernel<<<pb, 256>>>(Zf, natoms, adiv, apow, c1, c2, c3, c4, a1, a2, a3, a4);

    cudaMemsetAsync(d_out, 0, (size_t)out_size * sizeof(float));

    long nthreads = ((long)P + PPT - 1) / PPT;
    int blocks = (int)((nthreads + TPB - 1) / TPB);
    pair_kernel<<<blocks, TPB, SMEM_ATOMS>>>(rij, cutv, ii, jj, out, P);
}